// round 3
// baseline (speedup 1.0000x reference)
#include <cuda_runtime.h>

// Problem constants (fixed by the dataset)
#define NN 100000
#define EE 1600000
#define D  64
#define BN_EPS 1e-5f

// ---------------- scratch (static device globals; no allocation) ----------------
__device__ int   g_deg[NN];
__device__ float g_dis[NN];
__device__ int   g_rowptr[NN + 1];
__device__ int   g_fill[NN];
__device__ int   g_col[EE];
__device__ float g_wgt[EE];
__device__ __align__(16) float g_buf1[(size_t)NN * D];  // GEMM outputs (h1, h2)
__device__ __align__(16) float g_buf2[(size_t)NN * D];  // aggregation outputs
__device__ float g_bnsum[4 * D];  // [sum1 | sq1 | sum2 | sq2]

// ---------------- kernels ----------------

// Reset per-call state: deg=1 (self loop), fill=0, bn accumulators=0.
__global__ void k_init() {
    int stride = gridDim.x * blockDim.x;
    for (int i = blockIdx.x * blockDim.x + threadIdx.x; i < NN; i += stride) {
        g_deg[i]  = 1;
        g_fill[i] = 0;
    }
    if (blockIdx.x == 0 && threadIdx.x < 4 * D) g_bnsum[threadIdx.x] = 0.0f;
}

// In-degree histogram over dst.
__global__ void k_count(const int* __restrict__ dst) {
    int stride = gridDim.x * blockDim.x;
    for (int e = blockIdx.x * blockDim.x + threadIdx.x; e < EE; e += stride)
        atomicAdd(&g_deg[dst[e]], 1);
}

// Single-block exclusive scan of (deg-1) -> rowptr; also dis = rsqrt(deg).
__global__ void k_scan_dis() {
    __shared__ int s[1024];
    __shared__ int carry;
    int t = threadIdx.x;
    if (t == 0) carry = 0;
    __syncthreads();
    const int nchunks = (NN + 1023) / 1024;
    for (int c = 0; c < nchunks; c++) {
        int idx = c * 1024 + t;
        int d = 0;
        if (idx < NN) {
            int dg = g_deg[idx];
            g_dis[idx] = rsqrtf((float)dg);
            d = dg - 1;  // edge count only (self loop handled separately)
        }
        s[t] = d;
        __syncthreads();
        #pragma unroll
        for (int off = 1; off < 1024; off <<= 1) {
            int v = (t >= off) ? s[t - off] : 0;
            __syncthreads();
            s[t] += v;
            __syncthreads();
        }
        if (idx < NN) g_rowptr[idx] = carry + s[t] - d;  // exclusive
        int tot = s[1023];
        __syncthreads();
        if (t == 0) carry += tot;
        __syncthreads();
    }
    if (t == 0) g_rowptr[NN] = carry;
}

// Scatter edges into CSR buckets; precompute edge weight dis[src]*dis[dst].
__global__ void k_scatter(const int* __restrict__ src, const int* __restrict__ dst) {
    int stride = gridDim.x * blockDim.x;
    for (int e = blockIdx.x * blockDim.x + threadIdx.x; e < EE; e += stride) {
        int s = src[e];
        int d = dst[e];
        int p = atomicAdd(&g_fill[d], 1);
        int o = g_rowptr[d] + p;
        g_col[o] = s;
        g_wgt[o] = g_dis[s] * g_dis[d];
    }
}

// GEMM: out(g_buf1) = X @ W.  mode 0: X = x_ext (raw).  mode 1: X = g_buf2 with
// fused BatchNorm(stats at g_bnsum[0..127]) + ReLU applied to the input read.
// One warp per row; lane owns 2 output columns; W cached in shared.
__global__ void k_gemm(const float* __restrict__ X_ext,
                       const float* __restrict__ W,
                       const float* __restrict__ gamma,
                       const float* __restrict__ beta,
                       int mode) {
    __shared__ __align__(16) float ws[D * D];
    __shared__ float s_sc[D], s_sh[D];
    int t = threadIdx.x;
    for (int i = t; i < D * D / 4; i += blockDim.x)
        ((float4*)ws)[i] = ((const float4*)W)[i];
    if (mode == 1 && t < D) {
        float inv_n = 1.0f / (float)NN;
        float mu  = g_bnsum[t] * inv_n;
        float var = g_bnsum[D + t] * inv_n - mu * mu;
        float sc  = gamma[t] * rsqrtf(var + BN_EPS);
        s_sc[t] = sc;
        s_sh[t] = beta[t] - mu * sc;
    }
    __syncthreads();

    int warp = t >> 5, lane = t & 31;
    int wpb = blockDim.x >> 5;
    int stride = gridDim.x * wpb;
    const float* X = (mode == 0) ? X_ext : g_buf2;
    for (int row = blockIdx.x * wpb + warp; row < NN; row += stride) {
        float2 xr = ((const float2*)(X + (size_t)row * D))[lane];
        if (mode == 1) {
            xr.x = fmaxf(fmaf(xr.x, s_sc[2 * lane],     s_sh[2 * lane]),     0.0f);
            xr.y = fmaxf(fmaf(xr.y, s_sc[2 * lane + 1], s_sh[2 * lane + 1]), 0.0f);
        }
        float2 acc = make_float2(0.0f, 0.0f);
        #pragma unroll
        for (int k = 0; k < D; k++) {
            float xv = __shfl_sync(0xffffffffu, (k & 1) ? xr.y : xr.x, k >> 1);
            float2 wv = ((const float2*)(ws + k * D))[lane];
            acc.x = fmaf(xv, wv.x, acc.x);
            acc.y = fmaf(xv, wv.y, acc.y);
        }
        ((float2*)(g_buf1 + (size_t)row * D))[lane] = acc;
    }
}

// Pull aggregation: g_buf2[n] = bias + dis[n]^2 * h[n] + sum_e w[e]*h[col[e]].
// One warp per node, lane owns 2 features. No atomics.
__global__ void k_agg(const float* __restrict__ bias) {
    int t = threadIdx.x;
    int warp = t >> 5, lane = t & 31;
    int wpb = blockDim.x >> 5;
    int stride = gridDim.x * wpb;
    const float* __restrict__ H = g_buf1;
    float2 b = ((const float2*)bias)[lane];
    for (int n = blockIdx.x * wpb + warp; n < NN; n += stride) {
        float dn = g_dis[n];
        float w0 = dn * dn;
        float2 hv = ((const float2*)(H + (size_t)n * D))[lane];
        float2 acc = make_float2(fmaf(w0, hv.x, b.x), fmaf(w0, hv.y, b.y));
        int s = g_rowptr[n], e = g_rowptr[n + 1];
        #pragma unroll 4
        for (int i = s; i < e; i++) {
            int   sc = __ldg(&g_col[i]);
            float w  = __ldg(&g_wgt[i]);
            float2 v = ((const float2*)(H + (size_t)sc * D))[lane];
            acc.x = fmaf(w, v.x, acc.x);
            acc.y = fmaf(w, v.y, acc.y);
        }
        ((float2*)(g_buf2 + (size_t)n * D))[lane] = acc;
    }
}

// Per-feature sum and sum-of-squares of g_buf2 -> g_bnsum[off .. off+127].
__global__ void k_stats(int off) {
    __shared__ float ss[256], sq[256];
    int t = threadIdx.x;
    float s = 0.0f, q = 0.0f;
    size_t total = (size_t)NN * D;
    size_t stride = (size_t)gridDim.x * 256;
    for (size_t i = (size_t)blockIdx.x * 256 + t; i < total; i += stride) {
        float v = g_buf2[i];
        s += v;
        q = fmaf(v, v, q);
    }
    ss[t] = s; sq[t] = q;
    __syncthreads();
    if (t < D) {
        s = ss[t] + ss[t + 64] + ss[t + 128] + ss[t + 192];
        q = sq[t] + sq[t + 64] + sq[t + 128] + sq[t + 192];
        atomicAdd(&g_bnsum[off + t], s);
        atomicAdd(&g_bnsum[off + D + t], q);
    }
}

// Final BN+ReLU from g_buf2 (stats at g_bnsum[128..255]) -> d_out.
__global__ void k_apply(float* __restrict__ out,
                        const float* __restrict__ gamma,
                        const float* __restrict__ beta) {
    __shared__ float s_sc[D], s_sh[D];
    int t = threadIdx.x;
    if (t < D) {
        float inv_n = 1.0f / (float)NN;
        float mu  = g_bnsum[128 + t] * inv_n;
        float var = g_bnsum[192 + t] * inv_n - mu * mu;
        float sc  = gamma[t] * rsqrtf(var + BN_EPS);
        s_sc[t] = sc;
        s_sh[t] = beta[t] - mu * sc;
    }
    __syncthreads();
    int f = t & 63;
    size_t total = (size_t)NN * D;
    size_t stride = (size_t)gridDim.x * blockDim.x;
    for (size_t i = (size_t)blockIdx.x * blockDim.x + t; i < total; i += stride) {
        out[i] = fmaxf(fmaf(g_buf2[i], s_sc[f], s_sh[f]), 0.0f);
    }
}

// ---------------- launch ----------------
extern "C" void kernel_launch(void* const* d_in, const int* in_sizes, int n_in,
                              void* d_out, int out_size) {
    const float* x   = (const float*)d_in[0];
    const int*   ei  = (const int*)  d_in[1];
    const float* W1  = (const float*)d_in[2];
    const float* b1  = (const float*)d_in[3];
    const float* ga1 = (const float*)d_in[4];
    const float* be1 = (const float*)d_in[5];
    const float* W2  = (const float*)d_in[6];
    const float* b2  = (const float*)d_in[7];
    const float* ga2 = (const float*)d_in[8];
    const float* be2 = (const float*)d_in[9];
    float* out = (float*)d_out;

    const int* src = ei;        // edge_index[0]
    const int* dst = ei + EE;   // edge_index[1]

    const int TB = 256;
    const int GEMM_BLKS = (NN + 7) / 8;   // warp per row, 8 warps/block
    const int AGG_BLKS  = (NN + 7) / 8;   // warp per node

    // CSR build
    k_init   <<<256, TB>>>();
    k_count  <<<2048, TB>>>(dst);
    k_scan_dis<<<1, 1024>>>();
    k_scatter<<<2048, TB>>>(src, dst);

    // Layer 1
    k_gemm <<<GEMM_BLKS, TB>>>(x, W1, nullptr, nullptr, 0);   // buf1 = x@W1
    k_agg  <<<AGG_BLKS,  TB>>>(b1);                           // buf2 = agg(buf1)+b1
    k_stats<<<512, TB>>>(0);

    // Layer 2 (BN1+ReLU fused into GEMM input)
    k_gemm <<<GEMM_BLKS, TB>>>(nullptr, W2, ga1, be1, 1);     // buf1 = relu(bn(buf2))@W2
    k_agg  <<<AGG_BLKS,  TB>>>(b2);                           // buf2 = agg(buf1)+b2
    k_stats<<<512, TB>>>(128);

    // Output
    k_apply<<<2048, TB>>>(out, ga2, be2);
}

// round 5
// speedup vs baseline: 1.4553x; 1.4553x over previous
#include <cuda_runtime.h>

// Problem constants (fixed by the dataset)
#define NN 100000
#define EE 1600000
#define D  64
#define BN_EPS 1e-5f
#define NCH 98   // ceil(NN / 1024)

// ---------------- scratch (static device globals; no allocation) ----------------
__device__ int   g_deg[NN];
__device__ float g_dis[NN];
__device__ int   g_rowptr[NN + 1];
__device__ int   g_fill[NN];
__device__ int   g_psum[128];
__device__ __align__(16) int2  g_cw[EE];                 // packed (col, wgt bits)
__device__ __align__(16) float g_buf1[(size_t)NN * D];   // GEMM outputs (h1, h2)
__device__ __align__(16) float g_buf2[(size_t)NN * D];   // aggregation outputs
__device__ float g_bnsum[4 * D];  // [sum1 | sq1 | sum2 | sq2]

// ---------------- kernels ----------------

// Reset per-call state: deg=1 (self loop), fill=0, bn accumulators=0.
__global__ void k_init() {
    int stride = gridDim.x * blockDim.x;
    for (int i = blockIdx.x * blockDim.x + threadIdx.x; i < NN; i += stride) {
        g_deg[i]  = 1;
        g_fill[i] = 0;
    }
    if (blockIdx.x == 0 && threadIdx.x < 4 * D) g_bnsum[threadIdx.x] = 0.0f;
    if (blockIdx.x == 0 && threadIdx.x == 0)    g_rowptr[NN] = EE;
}

// In-degree histogram over dst (int4 vectorized; EE % 4 == 0).
__global__ void k_count(const int4* __restrict__ dst4) {
    int stride = gridDim.x * blockDim.x;
    for (int e = blockIdx.x * blockDim.x + threadIdx.x; e < EE / 4; e += stride) {
        int4 d = __ldg(&dst4[e]);
        atomicAdd(&g_deg[d.x], 1);
        atomicAdd(&g_deg[d.y], 1);
        atomicAdd(&g_deg[d.z], 1);
        atomicAdd(&g_deg[d.w], 1);
    }
}

// Phase A: per-chunk (1024) partial sums of (deg-1); also dis = rsqrt(deg).
__global__ void k_prep() {
    __shared__ int s[1024];
    int t = threadIdx.x;
    int idx = blockIdx.x * 1024 + t;
    int d = 0;
    if (idx < NN) {
        int dg = g_deg[idx];
        g_dis[idx] = rsqrtf((float)dg);
        d = dg - 1;
    }
    s[t] = d;
    __syncthreads();
    #pragma unroll
    for (int off = 512; off > 0; off >>= 1) {
        if (t < off) s[t] += s[t + off];
        __syncthreads();
    }
    if (t == 0) g_psum[blockIdx.x] = s[0];
}

// Phase B: exclusive scan of the 98 chunk sums (single tiny block).
__global__ void k_scan_psum() {
    __shared__ int s[128];
    int t = threadIdx.x;
    s[t] = (t < NCH) ? g_psum[t] : 0;
    __syncthreads();
    #pragma unroll
    for (int off = 1; off < 128; off <<= 1) {
        int v = (t >= off) ? s[t - off] : 0;
        __syncthreads();
        s[t] += v;
        __syncthreads();
    }
    g_psum[t] = (t == 0) ? 0 : s[t - 1];
}

// Phase C: per-chunk rescan + offset -> exclusive rowptr.
__global__ void k_scan_apply() {
    __shared__ int s[1024];
    int t = threadIdx.x;
    int idx = blockIdx.x * 1024 + t;
    int d = (idx < NN) ? (g_deg[idx] - 1) : 0;
    s[t] = d;
    __syncthreads();
    #pragma unroll
    for (int off = 1; off < 1024; off <<= 1) {
        int v = (t >= off) ? s[t - off] : 0;
        __syncthreads();
        s[t] += v;
        __syncthreads();
    }
    if (idx < NN) g_rowptr[idx] = g_psum[blockIdx.x] + s[t] - d;
}

// Scatter edges into CSR buckets; pack (src, dis[src]*dis[dst]) into 8B.
__global__ void k_scatter(const int4* __restrict__ src4, const int4* __restrict__ dst4) {
    int stride = gridDim.x * blockDim.x;
    for (int e = blockIdx.x * blockDim.x + threadIdx.x; e < EE / 4; e += stride) {
        int4 sv = __ldg(&src4[e]);
        int4 dv = __ldg(&dst4[e]);
        int ss[4] = {sv.x, sv.y, sv.z, sv.w};
        int dd[4] = {dv.x, dv.y, dv.z, dv.w};
        #pragma unroll
        for (int j = 0; j < 4; j++) {
            int s = ss[j], d = dd[j];
            int p = atomicAdd(&g_fill[d], 1);
            int o = g_rowptr[d] + p;
            g_cw[o] = make_int2(s, __float_as_int(g_dis[s] * g_dis[d]));
        }
    }
}

// GEMM: g_buf1 = X @ W.  mode 0: X = x_ext.  mode 1: X = g_buf2 with fused
// BatchNorm(stats g_bnsum[0..127]) + ReLU on the input read.
// One warp per row (grid-stride); lane owns 2 output cols; W in shared.
__global__ void k_gemm(const float* __restrict__ X_ext,
                       const float* __restrict__ W,
                       const float* __restrict__ gamma,
                       const float* __restrict__ beta,
                       int mode) {
    __shared__ __align__(16) float ws[D * D];
    __shared__ float s_sc[D], s_sh[D];
    int t = threadIdx.x;
    for (int i = t; i < D * D / 4; i += blockDim.x)
        ((float4*)ws)[i] = ((const float4*)W)[i];
    if (mode == 1 && t < D) {
        float inv_n = 1.0f / (float)NN;
        float mu  = g_bnsum[t] * inv_n;
        float var = g_bnsum[D + t] * inv_n - mu * mu;
        float sc  = gamma[t] * rsqrtf(var + BN_EPS);
        s_sc[t] = sc;
        s_sh[t] = beta[t] - mu * sc;
    }
    __syncthreads();

    int warp = t >> 5, lane = t & 31;
    int wpb = blockDim.x >> 5;
    int stride = gridDim.x * wpb;
    const float* X = (mode == 0) ? X_ext : g_buf2;
    for (int row = blockIdx.x * wpb + warp; row < NN; row += stride) {
        float2 xr = ((const float2*)(X + (size_t)row * D))[lane];
        if (mode == 1) {
            xr.x = fmaxf(fmaf(xr.x, s_sc[2 * lane],     s_sh[2 * lane]),     0.0f);
            xr.y = fmaxf(fmaf(xr.y, s_sc[2 * lane + 1], s_sh[2 * lane + 1]), 0.0f);
        }
        float2 acc = make_float2(0.0f, 0.0f);
        #pragma unroll
        for (int k = 0; k < D; k++) {
            float xv = __shfl_sync(0xffffffffu, (k & 1) ? xr.y : xr.x, k >> 1);
            float2 wv = ((const float2*)(ws + k * D))[lane];
            acc.x = fmaf(xv, wv.x, acc.x);
            acc.y = fmaf(xv, wv.y, acc.y);
        }
        ((float2*)(g_buf1 + (size_t)row * D))[lane] = acc;
    }
}

// Pull aggregation with FUSED BN stats:
//   g_buf2[n] = bias + dis[n]^2 * h[n] + sum_e w[e]*h[col[e]]
// One warp per node (grid-stride), lane owns 2 features, no float atomics in
// the hot loop. Per-feature sum/sumsq reduced per block, one atomic per feature.
// Requires blockDim == 256.
__global__ void k_agg(const float* __restrict__ bias, int off) {
    __shared__ float ssum[8 * D], ssq[8 * D];
    int t = threadIdx.x;
    int warp = t >> 5, lane = t & 31;
    int stride = gridDim.x * 8;
    const float* __restrict__ H = g_buf1;
    float2 b = ((const float2*)bias)[lane];
    float2 ts = make_float2(0.0f, 0.0f);
    float2 tq = make_float2(0.0f, 0.0f);
    for (int n = blockIdx.x * 8 + warp; n < NN; n += stride) {
        float dn = g_dis[n];
        float w0 = dn * dn;
        float2 hv = ((const float2*)(H + (size_t)n * D))[lane];
        float2 acc = make_float2(fmaf(w0, hv.x, b.x), fmaf(w0, hv.y, b.y));
        int s0 = g_rowptr[n], e0 = g_rowptr[n + 1];
        #pragma unroll 8
        for (int i = s0; i < e0; i++) {
            int2  cw = __ldg(&g_cw[i]);
            float w  = __int_as_float(cw.y);
            float2 v = ((const float2*)(H + (size_t)cw.x * D))[lane];
            acc.x = fmaf(w, v.x, acc.x);
            acc.y = fmaf(w, v.y, acc.y);
        }
        ((float2*)(g_buf2 + (size_t)n * D))[lane] = acc;
        ts.x += acc.x;
        ts.y += acc.y;
        tq.x = fmaf(acc.x, acc.x, tq.x);
        tq.y = fmaf(acc.y, acc.y, tq.y);
    }
    ssum[warp * D + 2 * lane]     = ts.x;
    ssum[warp * D + 2 * lane + 1] = ts.y;
    ssq [warp * D + 2 * lane]     = tq.x;
    ssq [warp * D + 2 * lane + 1] = tq.y;
    __syncthreads();
    if (t < D) {
        float s = 0.0f, q = 0.0f;
        #pragma unroll
        for (int w = 0; w < 8; w++) {
            s += ssum[w * D + t];
            q += ssq [w * D + t];
        }
        atomicAdd(&g_bnsum[off + t],     s);
        atomicAdd(&g_bnsum[off + D + t], q);
    }
}

// Final BN+ReLU from g_buf2 (stats g_bnsum[128..255]) -> d_out. float4.
__global__ void k_apply(float4* __restrict__ out,
                        const float* __restrict__ gamma,
                        const float* __restrict__ beta) {
    __shared__ float s_sc[D], s_sh[D];
    int t = threadIdx.x;
    if (t < D) {
        float inv_n = 1.0f / (float)NN;
        float mu  = g_bnsum[128 + t] * inv_n;
        float var = g_bnsum[192 + t] * inv_n - mu * mu;
        float sc  = gamma[t] * rsqrtf(var + BN_EPS);
        s_sc[t] = sc;
        s_sh[t] = beta[t] - mu * sc;
    }
    __syncthreads();
    const float4* __restrict__ in = (const float4*)g_buf2;
    size_t total  = (size_t)NN * (D / 4);
    size_t stride = (size_t)gridDim.x * blockDim.x;
    for (size_t i = (size_t)blockIdx.x * blockDim.x + t; i < total; i += stride) {
        int f = ((int)i & 15) * 4;
        float4 v = in[i];
        v.x = fmaxf(fmaf(v.x, s_sc[f],     s_sh[f]),     0.0f);
        v.y = fmaxf(fmaf(v.y, s_sc[f + 1], s_sh[f + 1]), 0.0f);
        v.z = fmaxf(fmaf(v.z, s_sc[f + 2], s_sh[f + 2]), 0.0f);
        v.w = fmaxf(fmaf(v.w, s_sc[f + 3], s_sh[f + 3]), 0.0f);
        out[i] = v;
    }
}

// ---------------- launch ----------------
extern "C" void kernel_launch(void* const* d_in, const int* in_sizes, int n_in,
                              void* d_out, int out_size) {
    const float* x   = (const float*)d_in[0];
    const int*   ei  = (const int*)  d_in[1];
    const float* W1  = (const float*)d_in[2];
    const float* b1  = (const float*)d_in[3];
    const float* ga1 = (const float*)d_in[4];
    const float* be1 = (const float*)d_in[5];
    const float* W2  = (const float*)d_in[6];
    const float* b2  = (const float*)d_in[7];
    const float* ga2 = (const float*)d_in[8];
    const float* be2 = (const float*)d_in[9];
    float* out = (float*)d_out;

    const int4* src4 = (const int4*)ei;         // edge_index[0]
    const int4* dst4 = (const int4*)(ei + EE);  // edge_index[1]

    const int TB = 256;
    const int WORK_BLKS = 1480;  // grid-stride for gemm/agg

    // CSR build
    k_init      <<<256, TB>>>();
    k_count     <<<1024, TB>>>(dst4);
    k_prep      <<<NCH, 1024>>>();
    k_scan_psum <<<1, 128>>>();
    k_scan_apply<<<NCH, 1024>>>();
    k_scatter   <<<1024, TB>>>(src4, dst4);

    // Layer 1
    k_gemm <<<WORK_BLKS, TB>>>(x, W1, nullptr, nullptr, 0);   // buf1 = x@W1
    k_agg  <<<WORK_BLKS, TB>>>(b1, 0);                        // buf2 = agg(buf1)+b1, stats->[0:128)

    // Layer 2 (BN1+ReLU fused into GEMM input)
    k_gemm <<<WORK_BLKS, TB>>>(nullptr, W2, ga1, be1, 1);     // buf1 = relu(bn(buf2))@W2
    k_agg  <<<WORK_BLKS, TB>>>(b2, 128);                      // buf2 = agg(buf1)+b2, stats->[128:256)

    // Output
    k_apply<<<2048, TB>>>((float4*)out, ga2, be2);
}